// round 13
// baseline (speedup 1.0000x reference)
#include <cuda_runtime.h>
#include <cuda_bf16.h>
#include <stdint.h>

#define Bn 64
#define Cn 128
#define Hn 56
#define Wn 56
#define HWn (Hn*Wn)

#define ROWS 4
#define TILE_N (ROWS*Wn)
#define ACT_ROWS (ROWS+2)
#define ACT_W (Wn+2)
#define ACT_PIX (ACT_ROWS*ACT_W)
#define ACT_STRIDE 272
#define W_STRIDE 272
#define WBUF_BYTES (128*W_STRIDE)
#define ACT_BYTES (ACT_PIX*ACT_STRIDE)
#define NSTAGE 3
#define SMEM_BYTES (ACT_BYTES + NSTAGE*WBUF_BYTES)
#define STAGE_STRIDE 132
#define XCH 37                 // xres channels per staged buffer
#define XSTRIDE 928            // bytes per staged channel chunk (58*16)

__device__ __align__(16) uint4 g_bits1[Bn*HWn];
__device__ __align__(16) uint4 g_bits2[Bn*HWn];
__device__ __align__(16) __nv_bfloat16 g_w1[9*128*128];
__device__ __align__(16) __nv_bfloat16 g_w2[9*128*128];

__device__ __forceinline__ uint32_t smem_u32(const void* p){
    return (uint32_t)__cvta_generic_to_shared(p);
}
__device__ __forceinline__ void ldsm4(uint32_t* r, uint32_t addr){
    asm volatile("ldmatrix.sync.aligned.m8n8.x4.shared.b16 {%0,%1,%2,%3},[%4];"
        : "=r"(r[0]),"=r"(r[1]),"=r"(r[2]),"=r"(r[3]) : "r"(addr));
}
__device__ __forceinline__ void mma16816(float* d, const uint32_t* a, const uint32_t* b){
    asm volatile("mma.sync.aligned.m16n8k16.row.col.f32.bf16.bf16.f32 "
        "{%0,%1,%2,%3},{%4,%5,%6,%7},{%8,%9},{%0,%1,%2,%3};"
        : "+f"(d[0]),"+f"(d[1]),"+f"(d[2]),"+f"(d[3])
        : "r"(a[0]),"r"(a[1]),"r"(a[2]),"r"(a[3]),"r"(b[0]),"r"(b[1]));
}
__device__ __forceinline__ void cpasync16(uint32_t s, const void* g){
    asm volatile("cp.async.cg.shared.global [%0],[%1],16;" :: "r"(s), "l"(g));
}
__device__ __forceinline__ void cpcommit(){ asm volatile("cp.async.commit_group;"); }
template<int N> __device__ __forceinline__ void cpwait(){
    asm volatile("cp.async.wait_group %0;" :: "n"(N));
}

// merged weight-sign prep (blocks 0..575) + activation pack (blocks 576..1359)
__global__ void prep(const float* __restrict__ x,
                     const float* __restrict__ w1, const float* __restrict__ w2){
    int blk = blockIdx.x;
    if (blk < 576){
        int i = blk*256 + threadIdx.x;
        if (i >= 9*128*128) return;
        int c = i & 127;
        int o = (i >> 7) & 127;
        int t = i >> 14;
        int s = ((o*128 + c)*3 + t/3)*3 + (t%3);
        float a = w1[s], b = w2[s];
        g_w1[i] = __float2bfloat16((a>0.f)?1.f:((a<0.f)?-1.f:0.f));
        g_w2[i] = __float2bfloat16((b>0.f)?1.f:((b<0.f)?-1.f:0.f));
    } else {
        int p = (blk-576)*256 + threadIdx.x;
        if (p >= Bn*HWn) return;
        int b  = p / HWn;
        int hw = p - b*HWn;
        const float* base = x + (size_t)b*Cn*HWn + hw;
        uint32_t w0=0,wv1=0,wv2=0,wv3=0;
        #pragma unroll
        for (int c=0;c<32;c++)  w0  |= (base[(size_t)(c    )*HWn] < 0.f ? 1u:0u) << c;
        #pragma unroll
        for (int c=0;c<32;c++)  wv1 |= (base[(size_t)(c+32 )*HWn] < 0.f ? 1u:0u) << c;
        #pragma unroll
        for (int c=0;c<32;c++)  wv2 |= (base[(size_t)(c+64 )*HWn] < 0.f ? 1u:0u) << c;
        #pragma unroll
        for (int c=0;c<32;c++)  wv3 |= (base[(size_t)(c+96 )*HWn] < 0.f ? 1u:0u) << c;
        g_bits1[p] = make_uint4(w0,wv1,wv2,wv3);
    }
}

template<int PASS>
__global__ void __launch_bounds__(256,1)
conv_bin(const float* __restrict__ gamma, const float* __restrict__ beta,
         const float* __restrict__ mean,  const float* __restrict__ var,
         const float* __restrict__ xres,  float* __restrict__ out)
{
    extern __shared__ char smem[];
    char* act = smem;
    char* wsm = smem + ACT_BYTES;

    const int tid  = threadIdx.x;
    const int lane = tid & 31;
    const int warp = tid >> 5;
    const int wm   = warp & 3;
    const int wn   = warp >> 2;
    const int b    = blockIdx.y;
    const int y0   = blockIdx.x * ROWS;

    const uint4* bits_in = (PASS==1) ? g_bits1 : g_bits2;
    const __nv_bfloat16* wg = (PASS==1) ? g_w1 : g_w2;

    // prefetch weight taps 0,1 into stage buffers 0,1
    {
        const char* gsrc = (const char*)wg;
        uint32_t wb = smem_u32(wsm);
        #pragma unroll
        for (int i=0;i<8;i++){
            int e = i*256 + tid;
            cpasync16(wb + (e>>4)*W_STRIDE + (e&15)*16, gsrc + (size_t)e*16);
        }
        cpcommit();
        gsrc += 32768;
        #pragma unroll
        for (int i=0;i<8;i++){
            int e = i*256 + tid;
            cpasync16(wb + WBUF_BYTES + (e>>4)*W_STRIDE + (e&15)*16, gsrc + (size_t)e*16);
        }
        cpcommit();
    }

    // expand sign bits -> bf16 (+1/-1), pads=0
    for (int idx = tid; idx < ACT_PIX; idx += 256){
        int r  = idx / ACT_W;
        int xc = idx - r*ACT_W;
        int gy = y0 - 1 + r;
        int gx = xc - 1;
        uint4 bw = make_uint4(0,0,0,0);
        bool valid = ((unsigned)gy < (unsigned)Hn) && ((unsigned)gx < (unsigned)Wn);
        if (valid) bw = bits_in[(b*Hn + gy)*Wn + gx];
        uint32_t* dst = (uint32_t*)(act + (size_t)idx*ACT_STRIDE);
        uint32_t arr[4] = {bw.x, bw.y, bw.z, bw.w};
        #pragma unroll
        for (int g=0;g<4;g++){
            uint32_t bwv = arr[g];
            #pragma unroll
            for (int j=0;j<16;j++){
                uint32_t b2 = (bwv >> (2*j)) & 3u;
                uint32_t pr = valid ? (0x3F803F80u | ((b2&1u)<<15) | ((b2>>1)<<31)) : 0u;
                dst[g*16 + j] = pr;
            }
        }
    }

    const uint32_t act_base = smem_u32(act);
    const uint32_t w_base   = smem_u32(wsm);
    const uint32_t aoff = (uint32_t)(wm*32 + (lane&15))*W_STRIDE + (uint32_t)(lane>>4)*16;

    float acc[2][14][4];
    #pragma unroll
    for (int i=0;i<2;i++)
        #pragma unroll
        for (int j=0;j<14;j++)
            #pragma unroll
            for (int e=0;e<4;e++) acc[i][j][e] = 0.f;

    const int bsel = (lane >> 4) & 1;
    const int brow = lane & 7;
    const int bk16 = (lane >> 3) & 1;

    const float* xtile = xres + ((size_t)(b*Cn)*Hn + (size_t)y0)*Wn;

    for (int t=0; t<9; ++t){
        cpwait<1>();
        __syncthreads();   // tap t weights visible; tap t-1 reads done

        if (t+2 < 9){
            const char* gsrc = (const char*)(wg + (size_t)(t+2)*16384);
            uint32_t sdst = w_base + (uint32_t)((t+2)%NSTAGE)*WBUF_BYTES;
            #pragma unroll
            for (int i=0;i<8;i++){
                int e = i*256 + tid;
                cpasync16(sdst + (e>>4)*W_STRIDE + (e&15)*16, gsrc + (size_t)e*16);
            }
        }
        // overlap: stage xres channels into freed weight buffers (PASS2)
        if (PASS == 2 && t >= 7){
            const int cb   = t - 7;                 // 0 -> buf0, 1 -> buf1
            uint32_t dstb  = w_base + (uint32_t)cb*WBUF_BYTES;
            const float* src0 = xtile + (size_t)cb*XCH*HWn;
            #pragma unroll
            for (int i=0;i<9;i++){
                int e = i*256 + tid;                // need e < 37*56 = 2072
                if (e < XCH*56){
                    int o = e/56, q = e - o*56;
                    cpasync16(dstb + (uint32_t)o*XSTRIDE + (uint32_t)q*16,
                              (const char*)(src0 + (size_t)o*HWn) + q*16);
                }
            }
        }
        cpcommit();

        const int dy = t/3, dx = t - dy*3;
        const uint32_t wb = w_base + (uint32_t)(t%NSTAGE)*WBUF_BYTES + aoff;

        uint32_t baddr[7];
        #pragma unroll
        for (int m=0;m<7;m++){
            int j  = 2*m + bsel;
            int ryj = wn*2 + ((j>=7)?1:0);
            int xs  = (j - ((j>=7)?7:0))*8;
            int pix0 = (ryj + dy)*ACT_W + xs + dx;
            baddr[m] = act_base + (uint32_t)(pix0 + brow)*ACT_STRIDE
                     + (uint32_t)bk16*16;
        }

        #pragma unroll
        for (int ks=0; ks<8; ks++){
            uint32_t a0[4], a1[4];
            ldsm4(a0, wb + ks*32);
            ldsm4(a1, wb + 16*W_STRIDE + ks*32);
            uint32_t bf[7][4];
            #pragma unroll
            for (int m=0;m<7;m++) ldsm4(bf[m], baddr[m] + ks*32);
            #pragma unroll
            for (int m=0;m<7;m++){
                mma16816(acc[0][2*m  ], a0, &bf[m][0]);
                mma16816(acc[0][2*m+1], a0, &bf[m][2]);
                mma16816(acc[1][2*m  ], a1, &bf[m][0]);
                mma16816(acc[1][2*m+1], a1, &bf[m][2]);
            }
        }
    }

    const int gr = lane >> 2;
    const int ct = lane & 3;
    float inv[4], bia[4];
    #pragma unroll
    for (int k=0;k<4;k++){
        int o = wm*32 + (k>>1)*16 + (k&1)*8 + gr;
        float iv = gamma[o] / sqrtf(var[o] + 1e-5f);
        inv[k] = iv;
        bia[k] = beta[o] - mean[o]*iv;
    }

    if (PASS == 2){
        cpwait<0>();
        __syncthreads();            // staged xres visible to all threads
        const float* xs0 = (const float*)(wsm);
        const float* xs1 = (const float*)(wsm + WBUF_BYTES);
        #pragma unroll
        for (int mf=0; mf<2; mf++){
            #pragma unroll
            for (int j=0;j<14;j++){
                int ry = wn*2 + ((j>=7)?1:0);
                int xx = (j - ((j>=7)?7:0))*8 + ct*2;
                int y  = y0 + ry;
                int px = ry*56 + xx;
                #pragma unroll
                for (int h=0;h<2;h++){
                    int o = wm*32 + mf*16 + h*8 + gr;
                    int k = mf*2 + h;
                    size_t base = ((size_t)(b*Cn + o)*Hn + y)*Wn + xx;
                    #pragma unroll
                    for (int cc=0; cc<2; cc++){
                        float rv;
                        if (o < XCH)        rv = xs0[(size_t)o*(XSTRIDE/4) + px + cc];
                        else if (o < 2*XCH) rv = xs1[(size_t)(o-XCH)*(XSTRIDE/4) + px + cc];
                        else                rv = xres[base + cc];
                        float v = __fadd_rn(__fmul_rn(acc[mf][j][h*2+cc], inv[k]), bia[k]);
                        v += rv;
                        v = fminf(fmaxf(v, -1.0f), 1.0f);
                        out[base + cc] = v;
                    }
                }
            }
        }
    } else {
        char* stage = wsm;   // weights no longer needed
        __syncthreads();     // all warps done reading weight buffers
        #pragma unroll
        for (int mf=0; mf<2; mf++){
            #pragma unroll
            for (int j=0;j<14;j++){
                int nb = wn*112 + j*8 + ct*2;
                #pragma unroll
                for (int h=0;h<2;h++){
                    int o = wm*32 + mf*16 + h*8 + gr;
                    int k = mf*2 + h;
                    #pragma unroll
                    for (int cc=0; cc<2; cc++){
                        float v = __fadd_rn(__fmul_rn(acc[mf][j][h*2+cc], inv[k]), bia[k]);
                        stage[(size_t)(nb+cc)*STAGE_STRIDE + o] = (v < 0.f) ? (char)1 : (char)0;
                    }
                }
            }
        }
        __syncthreads();
        if (tid < TILE_N){
            int n  = tid;
            int ry = n / 56;
            int xx = n - ry*56;
            int y  = y0 + ry;
            const uint32_t* src = (const uint32_t*)(stage + (size_t)n*STAGE_STRIDE);
            uint32_t wd[4];
            #pragma unroll
            for (int g=0; g<4; g++){
                uint32_t wv = 0;
                #pragma unroll
                for (int i=0;i<8;i++){
                    unsigned nib = __dp4a(src[g*8 + i], 0x08040201u, 0u);
                    wv |= nib << (4*i);
                }
                wd[g] = wv;
            }
            g_bits2[(b*Hn + y)*Wn + xx] = make_uint4(wd[0],wd[1],wd[2],wd[3]);
        }
    }
}

extern "C" void kernel_launch(void* const* d_in, const int* in_sizes, int n_in,
                              void* d_out, int out_size)
{
    const float* x      = (const float*)d_in[0];
    const float* w1     = (const float*)d_in[1];
    const float* w2     = (const float*)d_in[2];
    const float* gamma1 = (const float*)d_in[3];
    const float* beta1  = (const float*)d_in[4];
    const float* mean1  = (const float*)d_in[5];
    const float* var1   = (const float*)d_in[6];
    const float* gamma2 = (const float*)d_in[7];
    const float* beta2  = (const float*)d_in[8];
    const float* mean2  = (const float*)d_in[9];
    const float* var2   = (const float*)d_in[10];
    float* out = (float*)d_out;

    cudaFuncSetAttribute(conv_bin<1>, cudaFuncAttributeMaxDynamicSharedMemorySize, SMEM_BYTES);
    cudaFuncSetAttribute(conv_bin<2>, cudaFuncAttributeMaxDynamicSharedMemorySize, SMEM_BYTES);

    prep<<<1360, 256>>>(x, w1, w2);

    dim3 grid(Hn/ROWS, Bn);
    conv_bin<1><<<grid, 256, SMEM_BYTES>>>(gamma1, beta1, mean1, var1, x, out);
    conv_bin<2><<<grid, 256, SMEM_BYTES>>>(gamma2, beta2, mean2, var2, x, out);
}

// round 14
// speedup vs baseline: 1.0949x; 1.0949x over previous
#include <cuda_runtime.h>
#include <cuda_bf16.h>
#include <stdint.h>

#define Bn 64
#define Cn 128
#define Hn 56
#define Wn 56
#define HWn (Hn*Wn)

#define ROWS 4
#define TILE_N (ROWS*Wn)
#define ACT_ROWS (ROWS+2)
#define ACT_W (Wn+2)
#define ACT_PIX (ACT_ROWS*ACT_W)
#define ACT_STRIDE 272
#define W_STRIDE 272
#define WBUF_BYTES (128*W_STRIDE)
#define ACT_BYTES (ACT_PIX*ACT_STRIDE)
#define NSTAGE 3
#define SMEM_BYTES (ACT_BYTES + NSTAGE*WBUF_BYTES)
#define STAGE_STRIDE 132
#define NJOBS 1792
#define NCTA 148

__device__ __align__(16) uint4 g_bits1[Bn*HWn];
__device__ __align__(16) uint4 g_bits2[Bn*HWn];
__device__ __align__(16) __nv_bfloat16 g_w1[9*128*128];
__device__ __align__(16) __nv_bfloat16 g_w2[9*128*128];
__device__ int g_ctr;
__device__ volatile int g_flags[896];

__device__ __forceinline__ uint32_t smem_u32(const void* p){
    return (uint32_t)__cvta_generic_to_shared(p);
}
__device__ __forceinline__ void ldsm4(uint32_t* r, uint32_t addr){
    asm volatile("ldmatrix.sync.aligned.m8n8.x4.shared.b16 {%0,%1,%2,%3},[%4];"
        : "=r"(r[0]),"=r"(r[1]),"=r"(r[2]),"=r"(r[3]) : "r"(addr));
}
__device__ __forceinline__ void mma16816(float* d, const uint32_t* a, const uint32_t* b){
    asm volatile("mma.sync.aligned.m16n8k16.row.col.f32.bf16.bf16.f32 "
        "{%0,%1,%2,%3},{%4,%5,%6,%7},{%8,%9},{%0,%1,%2,%3};"
        : "+f"(d[0]),"+f"(d[1]),"+f"(d[2]),"+f"(d[3])
        : "r"(a[0]),"r"(a[1]),"r"(a[2]),"r"(a[3]),"r"(b[0]),"r"(b[1]));
}
__device__ __forceinline__ void cpasync16(uint32_t s, const void* g){
    asm volatile("cp.async.cg.shared.global [%0],[%1],16;" :: "r"(s), "l"(g));
}
__device__ __forceinline__ void cpcommit(){ asm volatile("cp.async.commit_group;"); }
template<int N> __device__ __forceinline__ void cpwait(){
    asm volatile("cp.async.wait_group %0;" :: "n"(N));
}

// merged prep: weight signs (blocks 0..575), pack x (blocks 576..1359),
// plus counter/flag reset for the persistent kernel (graph-replay safe)
__global__ void prep(const float* __restrict__ x,
                     const float* __restrict__ w1, const float* __restrict__ w2){
    int blk = blockIdx.x;
    if (blk < 4){
        int f = blk*256 + threadIdx.x;
        if (f < 896) g_flags[f] = 0;
        if (blk==0 && threadIdx.x==0) g_ctr = 0;
    }
    if (blk < 576){
        int i = blk*256 + threadIdx.x;
        if (i >= 9*128*128) return;
        int c = i & 127;
        int o = (i >> 7) & 127;
        int t = i >> 14;
        int s = ((o*128 + c)*3 + t/3)*3 + (t%3);
        float a = w1[s], b = w2[s];
        g_w1[i] = __float2bfloat16((a>0.f)?1.f:((a<0.f)?-1.f:0.f));
        g_w2[i] = __float2bfloat16((b>0.f)?1.f:((b<0.f)?-1.f:0.f));
    } else {
        int p = (blk-576)*256 + threadIdx.x;
        if (p >= Bn*HWn) return;
        int b  = p / HWn;
        int hw = p - b*HWn;
        const float* base = x + (size_t)b*Cn*HWn + hw;
        uint32_t w0=0,wv1=0,wv2=0,wv3=0;
        #pragma unroll
        for (int c=0;c<32;c++)  w0  |= (base[(size_t)(c    )*HWn] < 0.f ? 1u:0u) << c;
        #pragma unroll
        for (int c=0;c<32;c++)  wv1 |= (base[(size_t)(c+32 )*HWn] < 0.f ? 1u:0u) << c;
        #pragma unroll
        for (int c=0;c<32;c++)  wv2 |= (base[(size_t)(c+64 )*HWn] < 0.f ? 1u:0u) << c;
        #pragma unroll
        for (int c=0;c<32;c++)  wv3 |= (base[(size_t)(c+96 )*HWn] < 0.f ? 1u:0u) << c;
        g_bits1[p] = make_uint4(w0,wv1,wv2,wv3);
    }
}

__global__ void __launch_bounds__(256,1)
conv_fused(const float* __restrict__ g1, const float* __restrict__ be1,
           const float* __restrict__ m1, const float* __restrict__ v1,
           const float* __restrict__ g2, const float* __restrict__ be2,
           const float* __restrict__ m2, const float* __restrict__ v2,
           const float* __restrict__ xres, float* __restrict__ out)
{
    extern __shared__ char smem[];
    char* act = smem;
    char* wsm = smem + ACT_BYTES;
    __shared__ int s_job;

    const int tid  = threadIdx.x;
    const int lane = tid & 31;
    const int warp = tid >> 5;
    const int wm   = warp & 3;
    const int wn   = warp >> 2;
    const uint32_t act_base = smem_u32(act);
    const uint32_t w_base   = smem_u32(wsm);
    const uint32_t aoff = (uint32_t)(wm*32 + (lane&15))*W_STRIDE + (uint32_t)(lane>>4)*16;
    const int bsel = (lane >> 4) & 1;
    const int brow = lane & 7;
    const int bk16 = (lane >> 3) & 1;
    const int gr = lane >> 2;
    const int ct = lane & 3;

    for (;;){
        if (tid == 0) s_job = atomicAdd(&g_ctr, 1);
        __syncthreads();
        const int job = s_job;
        if (job >= NJOBS) return;
        const int pass = (job >= 896) ? 1 : 0;
        const int j  = pass ? job - 896 : job;
        const int b  = j / 14;
        const int ty = j - b*14;
        const int y0 = ty * ROWS;

        // conv2 jobs: wait for producer conv1 tiles (ty-1..ty+1 of batch b)
        if (pass && tid < 3){
            int t2 = ty - 1 + tid;
            t2 = t2 < 0 ? 0 : (t2 > 13 ? 13 : t2);
            const int fi = b*14 + t2;
            while (g_flags[fi] == 0) {}
            __threadfence();
        }
        __syncthreads();

        const uint4* bits_in = pass ? g_bits2 : g_bits1;
        const __nv_bfloat16* wg = pass ? g_w2 : g_w1;
        const float* gamma = pass ? g2 : g1;
        const float* beta  = pass ? be2 : be1;
        const float* mean  = pass ? m2 : m1;
        const float* var   = pass ? v2 : v1;

        // prefetch weight taps 0,1
        {
            const char* gsrc = (const char*)wg;
            #pragma unroll
            for (int i=0;i<8;i++){
                int e = i*256 + tid;
                cpasync16(w_base + (e>>4)*W_STRIDE + (e&15)*16, gsrc + (size_t)e*16);
            }
            cpcommit();
            gsrc += 32768;
            #pragma unroll
            for (int i=0;i<8;i++){
                int e = i*256 + tid;
                cpasync16(w_base + WBUF_BYTES + (e>>4)*W_STRIDE + (e&15)*16, gsrc + (size_t)e*16);
            }
            cpcommit();
        }

        // expand sign bits -> bf16 (+1/-1), pads=0
        for (int idx = tid; idx < ACT_PIX; idx += 256){
            int r  = idx / ACT_W;
            int xc = idx - r*ACT_W;
            int gy = y0 - 1 + r;
            int gx = xc - 1;
            uint4 bw = make_uint4(0,0,0,0);
            bool valid = ((unsigned)gy < (unsigned)Hn) && ((unsigned)gx < (unsigned)Wn);
            if (valid) bw = bits_in[(b*Hn + gy)*Wn + gx];
            uint32_t* dst = (uint32_t*)(act + (size_t)idx*ACT_STRIDE);
            uint32_t arr[4] = {bw.x, bw.y, bw.z, bw.w};
            #pragma unroll
            for (int g=0;g<4;g++){
                uint32_t bwv = arr[g];
                #pragma unroll
                for (int jj=0;jj<16;jj++){
                    uint32_t b2 = (bwv >> (2*jj)) & 3u;
                    uint32_t pr = valid ? (0x3F803F80u | ((b2&1u)<<15) | ((b2>>1)<<31)) : 0u;
                    dst[g*16 + jj] = pr;
                }
            }
        }

        float acc[2][14][4];
        #pragma unroll
        for (int i=0;i<2;i++)
            #pragma unroll
            for (int jj=0;jj<14;jj++)
                #pragma unroll
                for (int e=0;e<4;e++) acc[i][jj][e] = 0.f;

        for (int t=0; t<9; ++t){
            cpwait<1>();
            __syncthreads();   // tap t visible; tap t-1 reads done

            if (t+2 < 9){
                const char* gsrc = (const char*)(wg + (size_t)(t+2)*16384);
                uint32_t sdst = w_base + (uint32_t)((t+2)%NSTAGE)*WBUF_BYTES;
                #pragma unroll
                for (int i=0;i<8;i++){
                    int e = i*256 + tid;
                    cpasync16(sdst + (e>>4)*W_STRIDE + (e&15)*16, gsrc + (size_t)e*16);
                }
            }
            cpcommit();

            const int dy = t/3, dx = t - dy*3;
            const uint32_t wb = w_base + (uint32_t)(t%NSTAGE)*WBUF_BYTES + aoff;

            uint32_t baddr[7];
            #pragma unroll
            for (int m=0;m<7;m++){
                int jf  = 2*m + bsel;
                int ryj = wn*2 + ((jf>=7)?1:0);
                int xs  = (jf - ((jf>=7)?7:0))*8;
                int pix0 = (ryj + dy)*ACT_W + xs + dx;
                baddr[m] = act_base + (uint32_t)(pix0 + brow)*ACT_STRIDE
                         + (uint32_t)bk16*16;
            }

            #pragma unroll
            for (int ks=0; ks<8; ks++){
                uint32_t a0[4], a1[4];
                ldsm4(a0, wb + ks*32);
                ldsm4(a1, wb + 16*W_STRIDE + ks*32);
                uint32_t bf[7][4];
                #pragma unroll
                for (int m=0;m<7;m++) ldsm4(bf[m], baddr[m] + ks*32);
                #pragma unroll
                for (int m=0;m<7;m++){
                    mma16816(acc[0][2*m  ], a0, &bf[m][0]);
                    mma16816(acc[0][2*m+1], a0, &bf[m][2]);
                    mma16816(acc[1][2*m  ], a1, &bf[m][0]);
                    mma16816(acc[1][2*m+1], a1, &bf[m][2]);
                }
            }
        }

        float inv[4], bia[4];
        #pragma unroll
        for (int k=0;k<4;k++){
            int o = wm*32 + (k>>1)*16 + (k&1)*8 + gr;
            float iv = gamma[o] / sqrtf(var[o] + 1e-5f);
            inv[k] = iv;
            bia[k] = beta[o] - mean[o]*iv;
        }

        if (pass){
            #pragma unroll
            for (int mf=0; mf<2; mf++){
                #pragma unroll
                for (int jj=0;jj<14;jj++){
                    int ry = wn*2 + ((jj>=7)?1:0);
                    int xx = (jj - ((jj>=7)?7:0))*8 + ct*2;
                    int y  = y0 + ry;
                    #pragma unroll
                    for (int h=0;h<2;h++){
                        int o = wm*32 + mf*16 + h*8 + gr;
                        int k = mf*2 + h;
                        size_t base = ((size_t)(b*Cn + o)*Hn + y)*Wn + xx;
                        #pragma unroll
                        for (int cc=0; cc<2; cc++){
                            float v = __fadd_rn(__fmul_rn(acc[mf][jj][h*2+cc], inv[k]), bia[k]);
                            v += xres[base + cc];
                            v = fminf(fmaxf(v, -1.0f), 1.0f);
                            out[base + cc] = v;
                        }
                    }
                }
            }
            __syncthreads();   // smem safe to reuse next job
        } else {
            char* stage = wsm;   // weights no longer needed this job
            __syncthreads();     // all warps done reading weight buffers
            #pragma unroll
            for (int mf=0; mf<2; mf++){
                #pragma unroll
                for (int jj=0;jj<14;jj++){
                    int nb = wn*112 + jj*8 + ct*2;
                    #pragma unroll
                    for (int h=0;h<2;h++){
                        int o = wm*32 + mf*16 + h*8 + gr;
                        int k = mf*2 + h;
                        #pragma unroll
                        for (int cc=0; cc<2; cc++){
                            float v = __fadd_rn(__fmul_rn(acc[mf][jj][h*2+cc], inv[k]), bia[k]);
                            stage[(size_t)(nb+cc)*STAGE_STRIDE + o] = (v < 0.f) ? (char)1 : (char)0;
                        }
                    }
                }
            }
            __syncthreads();
            if (tid < TILE_N){
                int n  = tid;
                int ry = n / 56;
                int xx = n - ry*56;
                int y  = y0 + ry;
                const uint32_t* src = (const uint32_t*)(stage + (size_t)n*STAGE_STRIDE);
                uint32_t wd[4];
                #pragma unroll
                for (int g=0; g<4; g++){
                    uint32_t wv = 0;
                    #pragma unroll
                    for (int i=0;i<8;i++){
                        unsigned nib = __dp4a(src[g*8 + i], 0x08040201u, 0u);
                        wv |= nib << (4*i);
                    }
                    wd[g] = wv;
                }
                g_bits2[(b*Hn + y)*Wn + xx] = make_uint4(wd[0],wd[1],wd[2],wd[3]);
            }
            __syncthreads();   // all bits2 stores for this tile issued
            if (tid == 0){
                __threadfence();                 // publish bits2 gpu-wide
                g_flags[b*14 + ty] = 1;          // release flag
            }
        }
    }
}

extern "C" void kernel_launch(void* const* d_in, const int* in_sizes, int n_in,
                              void* d_out, int out_size)
{
    const float* x      = (const float*)d_in[0];
    const float* w1     = (const float*)d_in[1];
    const float* w2     = (const float*)d_in[2];
    const float* gamma1 = (const float*)d_in[3];
    const float* beta1  = (const float*)d_in[4];
    const float* mean1  = (const float*)d_in[5];
    const float* var1   = (const float*)d_in[6];
    const float* gamma2 = (const float*)d_in[7];
    const float* beta2  = (const float*)d_in[8];
    const float* mean2  = (const float*)d_in[9];
    const float* var2   = (const float*)d_in[10];
    float* out = (float*)d_out;

    cudaFuncSetAttribute(conv_fused, cudaFuncAttributeMaxDynamicSharedMemorySize, SMEM_BYTES);

    prep<<<1360, 256>>>(x, w1, w2);
    conv_fused<<<NCTA, 256, SMEM_BYTES>>>(gamma1, beta1, mean1, var1,
                                          gamma2, beta2, mean2, var2, x, out);
}

// round 15
// speedup vs baseline: 1.1546x; 1.0545x over previous
#include <cuda_runtime.h>
#include <cuda_bf16.h>
#include <stdint.h>

#define Bn 64
#define Cn 128
#define Hn 56
#define Wn 56
#define HWn (Hn*Wn)

#define ROWS 2
#define TILE_N (ROWS*Wn)          // 112
#define ACT_ROWS (ROWS+2)         // 4
#define ACT_W (Wn+2)              // 58
#define ACT_PIX (ACT_ROWS*ACT_W)  // 232
#define ACT_STRIDE 144            // 64ch bf16 = 128B + 16B pad
#define W_STRIDE 144
#define WBUF_BYTES (128*W_STRIDE) // 18432 per stage (128 o-rows x 64 ch)
#define ACT_BYTES (ACT_PIX*ACT_STRIDE) // 33408
#define NSTAGE 3
#define SMEM_BYTES (ACT_BYTES + NSTAGE*WBUF_BYTES) // 88704 -> occupancy 2
#define STAGE_STRIDE 132
#define NT 256
#define NSTAGES_TOT 18            // 2 k-halves x 9 taps

__device__ __align__(16) uint4 g_bits1[Bn*HWn];
__device__ __align__(16) uint4 g_bits2[Bn*HWn];
// weights as [kh][tap][o][c64] sign bf16 (16KB per stage)
__device__ __align__(16) __nv_bfloat16 g_w1[NSTAGES_TOT*128*64];
__device__ __align__(16) __nv_bfloat16 g_w2[NSTAGES_TOT*128*64];

__device__ __forceinline__ uint32_t smem_u32(const void* p){
    return (uint32_t)__cvta_generic_to_shared(p);
}
__device__ __forceinline__ void ldsm4(uint32_t* r, uint32_t addr){
    asm volatile("ldmatrix.sync.aligned.m8n8.x4.shared.b16 {%0,%1,%2,%3},[%4];"
        : "=r"(r[0]),"=r"(r[1]),"=r"(r[2]),"=r"(r[3]) : "r"(addr));
}
__device__ __forceinline__ void ldsm2(uint32_t* r, uint32_t addr){
    asm volatile("ldmatrix.sync.aligned.m8n8.x2.shared.b16 {%0,%1},[%2];"
        : "=r"(r[0]),"=r"(r[1]) : "r"(addr));
}
__device__ __forceinline__ void mma16816(float* d, const uint32_t* a, const uint32_t* b){
    asm volatile("mma.sync.aligned.m16n8k16.row.col.f32.bf16.bf16.f32 "
        "{%0,%1,%2,%3},{%4,%5,%6,%7},{%8,%9},{%0,%1,%2,%3};"
        : "+f"(d[0]),"+f"(d[1]),"+f"(d[2]),"+f"(d[3])
        : "r"(a[0]),"r"(a[1]),"r"(a[2]),"r"(a[3]),"r"(b[0]),"r"(b[1]));
}
__device__ __forceinline__ void cpasync16(uint32_t s, const void* g){
    asm volatile("cp.async.cg.shared.global [%0],[%1],16;" :: "r"(s), "l"(g));
}
__device__ __forceinline__ void cpcommit(){ asm volatile("cp.async.commit_group;"); }
template<int N> __device__ __forceinline__ void cpwait(){
    asm volatile("cp.async.wait_group %0;" :: "n"(N));
}

// merged prep: weight signs -> [kh][tap][o][c64] (blocks 0..575), pack x (576..1359)
__global__ void prep(const float* __restrict__ x,
                     const float* __restrict__ w1, const float* __restrict__ w2){
    int blk = blockIdx.x;
    if (blk < 576){
        int i = blk*256 + threadIdx.x;
        if (i >= 9*128*128) return;
        int c = i & 127;
        int o = (i >> 7) & 127;
        int t = i >> 14;
        int s = ((o*128 + c)*3 + t/3)*3 + (t%3);
        int kh = c >> 6;
        int dst = ((kh*9 + t)*128 + o)*64 + (c & 63);
        float a = w1[s], b = w2[s];
        g_w1[dst] = __float2bfloat16((a>0.f)?1.f:((a<0.f)?-1.f:0.f));
        g_w2[dst] = __float2bfloat16((b>0.f)?1.f:((b<0.f)?-1.f:0.f));
    } else {
        int p = (blk-576)*256 + threadIdx.x;
        if (p >= Bn*HWn) return;
        int b  = p / HWn;
        int hw = p - b*HWn;
        const float* base = x + (size_t)b*Cn*HWn + hw;
        uint32_t w0=0,wv1=0,wv2=0,wv3=0;
        #pragma unroll
        for (int c=0;c<32;c++)  w0  |= (base[(size_t)(c    )*HWn] < 0.f ? 1u:0u) << c;
        #pragma unroll
        for (int c=0;c<32;c++)  wv1 |= (base[(size_t)(c+32 )*HWn] < 0.f ? 1u:0u) << c;
        #pragma unroll
        for (int c=0;c<32;c++)  wv2 |= (base[(size_t)(c+64 )*HWn] < 0.f ? 1u:0u) << c;
        #pragma unroll
        for (int c=0;c<32;c++)  wv3 |= (base[(size_t)(c+96 )*HWn] < 0.f ? 1u:0u) << c;
        g_bits1[p] = make_uint4(w0,wv1,wv2,wv3);
    }
}

template<int PASS>
__global__ void __launch_bounds__(NT,2)
conv_bin(const float* __restrict__ gamma, const float* __restrict__ beta,
         const float* __restrict__ mean,  const float* __restrict__ var,
         const float* __restrict__ xres,  float* __restrict__ out)
{
    extern __shared__ char smem[];
    char* act = smem;
    char* wsm = smem + ACT_BYTES;

    const int tid  = threadIdx.x;
    const int lane = tid & 31;
    const int warp = tid >> 5;     // 0..7
    const int wm   = warp & 3;     // M: o in [wm*32, wm*32+32)
    const int wn   = warp >> 2;    // N: output row y0+wn, wn in 0..1
    const int b    = blockIdx.y;
    const int y0   = blockIdx.x * ROWS;

    const uint4* bits_in = (PASS==1) ? g_bits1 : g_bits2;
    const __nv_bfloat16* wg = (PASS==1) ? g_w1 : g_w2;

    // prefetch weight stages 0,1 (each 16KB = 1024 16B-chunks; 4 iters x 256 thr)
    {
        const char* gsrc = (const char*)wg;
        #pragma unroll
        for (int i=0;i<4;i++){
            int e = i*NT + tid;
            cpasync16(smem_u32(wsm) + (e>>3)*W_STRIDE + (e&7)*16, gsrc + (size_t)e*16);
        }
        cpcommit();
        gsrc += 16384;
        #pragma unroll
        for (int i=0;i<4;i++){
            int e = i*NT + tid;
            cpasync16(smem_u32(wsm) + WBUF_BYTES + (e>>3)*W_STRIDE + (e&7)*16, gsrc + (size_t)e*16);
        }
        cpcommit();
    }

    const uint32_t act_base = smem_u32(act);
    const uint32_t w_base   = smem_u32(wsm);
    const uint32_t aoff = (uint32_t)(wm*32 + (lane&15))*W_STRIDE + (uint32_t)(lane>>4)*16;

    float acc[2][7][4];
    #pragma unroll
    for (int i=0;i<2;i++)
        #pragma unroll
        for (int j=0;j<7;j++)
            #pragma unroll
            for (int e=0;e<4;e++) acc[i][j][e] = 0.f;

    const int brow = lane & 7;
    const int bk16 = (lane >> 3) & 1;

    for (int s=0; s<NSTAGES_TOT; ++s){
        const int kh = s / 9;
        const int t  = s - kh*9;

        cpwait<1>();
        __syncthreads();   // stage s weights visible; all reads of stage s-1 & act done

        // (re)expand activation half at the start of each k-half
        if (t == 0){
            for (int idx = tid; idx < ACT_PIX; idx += NT){
                int r  = idx / ACT_W;
                int xc = idx - r*ACT_W;
                int gy = y0 - 1 + r;
                int gx = xc - 1;
                uint2 bw = make_uint2(0,0);
                bool valid = ((unsigned)gy < (unsigned)Hn) && ((unsigned)gx < (unsigned)Wn);
                if (valid) bw = ((const uint2*)&bits_in[(b*Hn + gy)*Wn + gx])[kh];
                uint32_t* dst = (uint32_t*)(act + (size_t)idx*ACT_STRIDE);
                uint32_t arr[2] = {bw.x, bw.y};
                #pragma unroll
                for (int g=0;g<2;g++){
                    uint32_t bwv = arr[g];
                    #pragma unroll
                    for (int j=0;j<16;j++){
                        uint32_t b2 = (bwv >> (2*j)) & 3u;
                        uint32_t pr = valid ? (0x3F803F80u | ((b2&1u)<<15) | ((b2>>1)<<31)) : 0u;
                        dst[g*16 + j] = pr;
                    }
                }
            }
            __syncthreads();   // act half ready
        }

        if (s+2 < NSTAGES_TOT){
            const char* gsrc = (const char*)(wg + (size_t)(s+2)*8192);
            uint32_t sdst = w_base + (uint32_t)((s+2)%NSTAGE)*WBUF_BYTES;
            #pragma unroll
            for (int i=0;i<4;i++){
                int e = i*NT + tid;
                cpasync16(sdst + (e>>3)*W_STRIDE + (e&7)*16, gsrc + (size_t)e*16);
            }
        }
        cpcommit();

        const int dy = t/3, dx = t - dy*3;
        const uint32_t wb = w_base + (uint32_t)(s%NSTAGE)*WBUF_BYTES + aoff;

        uint32_t baddr[7];
        #pragma unroll
        for (int j=0;j<7;j++){
            int pix0 = (wn + dy)*ACT_W + j*8 + dx;
            baddr[j] = act_base + (uint32_t)(pix0 + brow)*ACT_STRIDE + (uint32_t)bk16*16;
        }

        #pragma unroll
        for (int ks=0; ks<4; ks++){        // 64 ch = 4 x k16
            uint32_t a0[4], a1[4];
            ldsm4(a0, wb + ks*32);
            ldsm4(a1, wb + 16*W_STRIDE + ks*32);
            uint32_t bf[7][2];
            #pragma unroll
            for (int j=0;j<7;j++) ldsm2(bf[j], baddr[j] + ks*32);
            #pragma unroll
            for (int j=0;j<7;j++){
                mma16816(acc[0][j], a0, bf[j]);
                mma16816(acc[1][j], a1, bf[j]);
            }
        }
    }

    const int gr = lane >> 2;
    const int ct = lane & 3;
    float inv[4], bia[4];
    #pragma unroll
    for (int k=0;k<4;k++){
        int o = wm*32 + (k>>1)*16 + (k&1)*8 + gr;
        float iv = gamma[o] / sqrtf(var[o] + 1e-5f);
        inv[k] = iv;
        bia[k] = beta[o] - mean[o]*iv;
    }

    if (PASS == 2){
        const int y = y0 + wn;
        #pragma unroll
        for (int mf=0; mf<2; mf++){
            #pragma unroll
            for (int j=0;j<7;j++){
                int xx = j*8 + ct*2;
                #pragma unroll
                for (int h=0;h<2;h++){
                    int o = wm*32 + mf*16 + h*8 + gr;
                    int k = mf*2 + h;
                    size_t base = ((size_t)(b*Cn + o)*Hn + y)*Wn + xx;
                    #pragma unroll
                    for (int cc=0; cc<2; cc++){
                        float v = __fadd_rn(__fmul_rn(acc[mf][j][h*2+cc], inv[k]), bia[k]);
                        v += xres[base + cc];
                        v = fminf(fmaxf(v, -1.0f), 1.0f);
                        out[base + cc] = v;
                    }
                }
            }
        }
    } else {
        char* stage = wsm;   // weights no longer needed
        __syncthreads();     // all warps done reading weight buffers
        #pragma unroll
        for (int mf=0; mf<2; mf++){
            #pragma unroll
            for (int j=0;j<7;j++){
                int nb = wn*56 + j*8 + ct*2;
                #pragma unroll
                for (int h=0;h<2;h++){
                    int o = wm*32 + mf*16 + h*8 + gr;
                    int k = mf*2 + h;
                    #pragma unroll
                    for (int cc=0; cc<2; cc++){
                        float v = __fadd_rn(__fmul_rn(acc[mf][j][h*2+cc], inv[k]), bia[k]);
                        stage[(size_t)(nb+cc)*STAGE_STRIDE + o] = (v < 0.f) ? (char)1 : (char)0;
                    }
                }
            }
        }
        __syncthreads();
        if (tid < TILE_N){
            int n  = tid;
            int ry = n / 56;
            int xx = n - ry*56;
            int y  = y0 + ry;
            const uint32_t* src = (const uint32_t*)(stage + (size_t)n*STAGE_STRIDE);
            uint32_t wd[4];
            #pragma unroll
            for (int g=0; g<4; g++){
                uint32_t wv = 0;
                #pragma unroll
                for (int i=0;i<8;i++){
                    unsigned nib = __dp4a(src[g*8 + i], 0x08040201u, 0u);
                    wv |= nib << (4*i);
                }
                wd[g] = wv;
            }
            g_bits2[(b*Hn + y)*Wn + xx] = make_uint4(wd[0],wd[1],wd[2],wd[3]);
        }
    }
}

extern "C" void kernel_launch(void* const* d_in, const int* in_sizes, int n_in,
                              void* d_out, int out_size)
{
    const float* x      = (const float*)d_in[0];
    const float* w1     = (const float*)d_in[1];
    const float* w2     = (const float*)d_in[2];
    const float* gamma1 = (const float*)d_in[3];
    const float* beta1  = (const float*)d_in[4];
    const float* mean1  = (const float*)d_in[5];
    const float* var1   = (const float*)d_in[6];
    const float* gamma2 = (const float*)d_in[7];
    const float* beta2  = (const float*)d_in[8];
    const float* mean2  = (const float*)d_in[9];
    const float* var2   = (const float*)d_in[10];
    float* out = (float*)d_out;

    cudaFuncSetAttribute(conv_bin<1>, cudaFuncAttributeMaxDynamicSharedMemorySize, SMEM_BYTES);
    cudaFuncSetAttribute(conv_bin<2>, cudaFuncAttributeMaxDynamicSharedMemorySize, SMEM_BYTES);

    prep<<<1360, 256>>>(x, w1, w2);

    dim3 grid(Hn/ROWS, Bn);
    conv_bin<1><<<grid, NT, SMEM_BYTES>>>(gamma1, beta1, mean1, var1, x, out);
    conv_bin<2><<<grid, NT, SMEM_BYTES>>>(gamma2, beta2, mean2, var2, x, out);
}

// round 16
// speedup vs baseline: 1.2168x; 1.0539x over previous
#include <cuda_runtime.h>
#include <cuda_bf16.h>
#include <stdint.h>

#define Bn 64
#define Cn 128
#define Hn 56
#define Wn 56
#define HWn (Hn*Wn)

#define ROWS 4
#define TILE_N (ROWS*Wn)
#define ACT_ROWS (ROWS+2)
#define ACT_W (Wn+2)
#define ACT_PIX (ACT_ROWS*ACT_W)
#define ACT_STRIDE 272
#define W_STRIDE 272
#define WBUF_BYTES (128*W_STRIDE)
#define ACT_BYTES (ACT_PIX*ACT_STRIDE)
#define NSTAGE 3
#define SMEM_BYTES (ACT_BYTES + NSTAGE*WBUF_BYTES)
#define STAGE_STRIDE 132

__device__ __align__(16) uint4 g_bits1[Bn*HWn];
__device__ __align__(16) uint4 g_bits2[Bn*HWn];
__device__ __align__(16) __nv_bfloat16 g_w1[9*128*128];
__device__ __align__(16) __nv_bfloat16 g_w2[9*128*128];

__device__ __forceinline__ uint32_t smem_u32(const void* p){
    return (uint32_t)__cvta_generic_to_shared(p);
}
__device__ __forceinline__ void ldsm4(uint32_t* r, uint32_t addr){
    asm volatile("ldmatrix.sync.aligned.m8n8.x4.shared.b16 {%0,%1,%2,%3},[%4];"
        : "=r"(r[0]),"=r"(r[1]),"=r"(r[2]),"=r"(r[3]) : "r"(addr));
}
__device__ __forceinline__ void mma16816(float* d, const uint32_t* a, const uint32_t* b){
    asm volatile("mma.sync.aligned.m16n8k16.row.col.f32.bf16.bf16.f32 "
        "{%0,%1,%2,%3},{%4,%5,%6,%7},{%8,%9},{%0,%1,%2,%3};"
        : "+f"(d[0]),"+f"(d[1]),"+f"(d[2]),"+f"(d[3])
        : "r"(a[0]),"r"(a[1]),"r"(a[2]),"r"(a[3]),"r"(b[0]),"r"(b[1]));
}
__device__ __forceinline__ void cpasync16(uint32_t s, const void* g){
    asm volatile("cp.async.cg.shared.global [%0],[%1],16;" :: "r"(s), "l"(g));
}
__device__ __forceinline__ void cpcommit(){ asm volatile("cp.async.commit_group;"); }
template<int N> __device__ __forceinline__ void cpwait(){
    asm volatile("cp.async.wait_group %0;" :: "n"(N));
}

// merged prep: weight signs (blocks 0..575) + vectorized pack (blocks 576..771)
// pack: 4 pixels per thread via float4 loads (same bytes, 4x fewer LDG)
__global__ void prep(const float* __restrict__ x,
                     const float* __restrict__ w1, const float* __restrict__ w2){
    int blk = blockIdx.x;
    if (blk < 576){
        int i = blk*256 + threadIdx.x;
        if (i >= 9*128*128) return;
        int c = i & 127;
        int o = (i >> 7) & 127;
        int t = i >> 14;
        int s = ((o*128 + c)*3 + t/3)*3 + (t%3);
        float a = w1[s], b = w2[s];
        g_w1[i] = __float2bfloat16((a>0.f)?1.f:((a<0.f)?-1.f:0.f));
        g_w2[i] = __float2bfloat16((b>0.f)?1.f:((b<0.f)?-1.f:0.f));
    } else {
        int p4 = (blk-576)*256 + threadIdx.x;       // group of 4 pixels
        if (p4 >= Bn*HWn/4) return;
        int b   = p4 / (HWn/4);
        int hw  = (p4 - b*(HWn/4)) * 4;
        const float* base = x + (size_t)b*Cn*HWn + hw;
        uint32_t w[4][4] = {};
        #pragma unroll
        for (int c=0;c<128;c++){
            float4 v = *(const float4*)(base + (size_t)c*HWn);
            uint32_t bit = 1u << (c & 31);
            int g = c >> 5;
            if (v.x < 0.f) w[0][g] |= bit;
            if (v.y < 0.f) w[1][g] |= bit;
            if (v.z < 0.f) w[2][g] |= bit;
            if (v.w < 0.f) w[3][g] |= bit;
        }
        #pragma unroll
        for (int k=0;k<4;k++)
            g_bits1[(size_t)b*HWn + hw + k] = make_uint4(w[k][0],w[k][1],w[k][2],w[k][3]);
    }
}

template<int PASS>
__global__ void __launch_bounds__(256,1)
conv_bin(const float* __restrict__ gamma, const float* __restrict__ beta,
         const float* __restrict__ mean,  const float* __restrict__ var,
         const float* __restrict__ xres,  float* __restrict__ out)
{
    extern __shared__ char smem[];
    char* act = smem;
    char* wsm = smem + ACT_BYTES;

    const int tid  = threadIdx.x;
    const int lane = tid & 31;
    const int warp = tid >> 5;
    const int wm   = warp & 3;
    const int wn   = warp >> 2;
    const int b    = blockIdx.y;
    const int y0   = blockIdx.x * ROWS;

    const uint4* bits_in = (PASS==1) ? g_bits1 : g_bits2;
    const __nv_bfloat16* wg = (PASS==1) ? g_w1 : g_w2;

    // prefetch weight taps 0,1 into stage buffers 0,1
    {
        const char* gsrc = (const char*)wg;
        uint32_t wb = smem_u32(wsm);
        #pragma unroll
        for (int i=0;i<8;i++){
            int e = i*256 + tid;
            cpasync16(wb + (e>>4)*W_STRIDE + (e&15)*16, gsrc + (size_t)e*16);
        }
        cpcommit();
        gsrc += 32768;
        #pragma unroll
        for (int i=0;i<8;i++){
            int e = i*256 + tid;
            cpasync16(wb + WBUF_BYTES + (e>>4)*W_STRIDE + (e&15)*16, gsrc + (size_t)e*16);
        }
        cpcommit();
    }

    // expand sign bits -> bf16 (+1/-1), pads=0
    for (int idx = tid; idx < ACT_PIX; idx += 256){
        int r  = idx / ACT_W;
        int xc = idx - r*ACT_W;
        int gy = y0 - 1 + r;
        int gx = xc - 1;
        uint4 bw = make_uint4(0,0,0,0);
        bool valid = ((unsigned)gy < (unsigned)Hn) && ((unsigned)gx < (unsigned)Wn);
        if (valid) bw = bits_in[(b*Hn + gy)*Wn + gx];
        uint32_t* dst = (uint32_t*)(act + (size_t)idx*ACT_STRIDE);
        uint32_t arr[4] = {bw.x, bw.y, bw.z, bw.w};
        #pragma unroll
        for (int g=0;g<4;g++){
            uint32_t bwv = arr[g];
            #pragma unroll
            for (int j=0;j<16;j++){
                uint32_t b2 = (bwv >> (2*j)) & 3u;
                uint32_t pr = valid ? (0x3F803F80u | ((b2&1u)<<15) | ((b2>>1)<<31)) : 0u;
                dst[g*16 + j] = pr;
            }
        }
    }

    const uint32_t act_base = smem_u32(act);
    const uint32_t w_base   = smem_u32(wsm);
    const uint32_t aoff = (uint32_t)(wm*32 + (lane&15))*W_STRIDE + (uint32_t)(lane>>4)*16;

    float acc[2][14][4];
    #pragma unroll
    for (int i=0;i<2;i++)
        #pragma unroll
        for (int j=0;j<14;j++)
            #pragma unroll
            for (int e=0;e<4;e++) acc[i][j][e] = 0.f;

    const int bsel = (lane >> 4) & 1;
    const int brow = lane & 7;
    const int bk16 = (lane >> 3) & 1;

    for (int t=0; t<9; ++t){
        cpwait<1>();
        __syncthreads();    // tap t visible; tap t-1 reads done

        if (t+2 < 9){
            const char* gsrc = (const char*)(wg + (size_t)(t+2)*16384);
            uint32_t sdst = w_base + (uint32_t)((t+2)%NSTAGE)*WBUF_BYTES;
            #pragma unroll
            for (int i=0;i<8;i++){
                int e = i*256 + tid;
                cpasync16(sdst + (e>>4)*W_STRIDE + (e&15)*16, gsrc + (size_t)e*16);
            }
        }
        cpcommit();

        const int dy = t/3, dx = t - dy*3;
        const uint32_t wb = w_base + (uint32_t)(t%NSTAGE)*WBUF_BYTES + aoff;

        uint32_t baddr[7];
        #pragma unroll
        for (int m=0;m<7;m++){
            int j  = 2*m + bsel;
            int ryj = wn*2 + ((j>=7)?1:0);
            int xs  = (j - ((j>=7)?7:0))*8;
            int pix0 = (ryj + dy)*ACT_W + xs + dx;
            baddr[m] = act_base + (uint32_t)(pix0 + brow)*ACT_STRIDE
                     + (uint32_t)bk16*16;
        }

        #pragma unroll
        for (int ks=0; ks<8; ks++){
            uint32_t a0[4], a1[4];
            ldsm4(a0, wb + ks*32);
            ldsm4(a1, wb + 16*W_STRIDE + ks*32);
            uint32_t bf[7][4];
            #pragma unroll
            for (int m=0;m<7;m++) ldsm4(bf[m], baddr[m] + ks*32);
            #pragma unroll
            for (int m=0;m<7;m++){
                mma16816(acc[0][2*m  ], a0, &bf[m][0]);
                mma16816(acc[0][2*m+1], a0, &bf[m][2]);
                mma16816(acc[1][2*m  ], a1, &bf[m][0]);
                mma16816(acc[1][2*m+1], a1, &bf[m][2]);
            }
        }
    }

    const int gr = lane >> 2;
    const int ct = lane & 3;
    float inv[4], bia[4];
    #pragma unroll
    for (int k=0;k<4;k++){
        int o = wm*32 + (k>>1)*16 + (k&1)*8 + gr;
        float iv = gamma[o] / sqrtf(var[o] + 1e-5f);
        inv[k] = iv;
        bia[k] = beta[o] - mean[o]*iv;
    }

    if (PASS == 2){
        #pragma unroll
        for (int mf=0; mf<2; mf++){
            #pragma unroll
            for (int j=0;j<14;j++){
                int ry = wn*2 + ((j>=7)?1:0);
                int xx = (j - ((j>=7)?7:0))*8 + ct*2;
                int y  = y0 + ry;
                #pragma unroll
                for (int h=0;h<2;h++){
                    int o = wm*32 + mf*16 + h*8 + gr;
                    int k = mf*2 + h;
                    size_t base = ((size_t)(b*Cn + o)*Hn + y)*Wn + xx;
                    #pragma unroll
                    for (int cc=0; cc<2; cc++){
                        float v = __fadd_rn(__fmul_rn(acc[mf][j][h*2+cc], inv[k]), bia[k]);
                        v += xres[base + cc];
                        v = fminf(fmaxf(v, -1.0f), 1.0f);
                        __stcs(&out[base + cc], v);   // evict-first: keep L2 for xres
                    }
                }
            }
        }
    } else {
        char* stage = wsm;   // weights no longer needed
        __syncthreads();     // all warps done reading weight buffers
        #pragma unroll
        for (int mf=0; mf<2; mf++){
            #pragma unroll
            for (int j=0;j<14;j++){
                int nb = wn*112 + j*8 + ct*2;
                #pragma unroll
                for (int h=0;h<2;h++){
                    int o = wm*32 + mf*16 + h*8 + gr;
                    int k = mf*2 + h;
                    #pragma unroll
                    for (int cc=0; cc<2; cc++){
                        float v = __fadd_rn(__fmul_rn(acc[mf][j][h*2+cc], inv[k]), bia[k]);
                        stage[(size_t)(nb+cc)*STAGE_STRIDE + o] = (v < 0.f) ? (char)1 : (char)0;
                    }
                }
            }
        }
        __syncthreads();
        if (tid < TILE_N){
            int n  = tid;
            int ry = n / 56;
            int xx = n - ry*56;
            int y  = y0 + ry;
            const uint32_t* src = (const uint32_t*)(stage + (size_t)n*STAGE_STRIDE);
            uint32_t wd[4];
            #pragma unroll
            for (int g=0; g<4; g++){
                uint32_t wv = 0;
                #pragma unroll
                for (int i=0;i<8;i++){
                    unsigned nib = __dp4a(src[g*8 + i], 0x08040201u, 0u);
                    wv |= nib << (4*i);
                }
                wd[g] = wv;
            }
            g_bits2[(b*Hn + y)*Wn + xx] = make_uint4(wd[0],wd[1],wd[2],wd[3]);
        }
    }
}

extern "C" void kernel_launch(void* const* d_in, const int* in_sizes, int n_in,
                              void* d_out, int out_size)
{
    const float* x      = (const float*)d_in[0];
    const float* w1     = (const float*)d_in[1];
    const float* w2     = (const float*)d_in[2];
    const float* gamma1 = (const float*)d_in[3];
    const float* beta1  = (const float*)d_in[4];
    const float* mean1  = (const float*)d_in[5];
    const float* var1   = (const float*)d_in[6];
    const float* gamma2 = (const float*)d_in[7];
    const float* beta2  = (const float*)d_in[8];
    const float* mean2  = (const float*)d_in[9];
    const float* var2   = (const float*)d_in[10];
    float* out = (float*)d_out;

    cudaFuncSetAttribute(conv_bin<1>, cudaFuncAttributeMaxDynamicSharedMemorySize, SMEM_BYTES);
    cudaFuncSetAttribute(conv_bin<2>, cudaFuncAttributeMaxDynamicSharedMemorySize, SMEM_BYTES);

    prep<<<772, 256>>>(x, w1, w2);

    dim3 grid(Hn/ROWS, Bn);
    conv_bin<1><<<grid, 256, SMEM_BYTES>>>(gamma1, beta1, mean1, var1, x, out);
    conv_bin<2><<<grid, 256, SMEM_BYTES>>>(gamma2, beta2, mean2, var2, x, out);
}

// round 17
// speedup vs baseline: 1.3096x; 1.0762x over previous
#include <cuda_runtime.h>
#include <cuda_bf16.h>
#include <stdint.h>

#define Bn 64
#define Cn 128
#define Hn 56
#define Wn 56
#define HWn (Hn*Wn)

#define ROWS 4
#define TILE_N (ROWS*Wn)
#define ACT_ROWS (ROWS+2)
#define ACT_W (Wn+2)
#define ACT_PIX (ACT_ROWS*ACT_W)
#define ACT_STRIDE 272
#define W_STRIDE 272
#define WBUF_BYTES (128*W_STRIDE)
#define ACT_BYTES (ACT_PIX*ACT_STRIDE)
#define NSTAGE 3
#define SMEM_BYTES (ACT_BYTES + NSTAGE*WBUF_BYTES)
#define STAGE_STRIDE 132

__device__ __align__(16) uint4 g_bits1[Bn*HWn];
__device__ __align__(16) uint4 g_bits2[Bn*HWn];
__device__ __align__(16) __nv_bfloat16 g_w1[9*128*128];
__device__ __align__(16) __nv_bfloat16 g_w2[9*128*128];

__device__ __forceinline__ uint32_t smem_u32(const void* p){
    return (uint32_t)__cvta_generic_to_shared(p);
}
__device__ __forceinline__ void ldsm4(uint32_t* r, uint32_t addr){
    asm volatile("ldmatrix.sync.aligned.m8n8.x4.shared.b16 {%0,%1,%2,%3},[%4];"
        : "=r"(r[0]),"=r"(r[1]),"=r"(r[2]),"=r"(r[3]) : "r"(addr));
}
__device__ __forceinline__ void mma16816(float* d, const uint32_t* a, const uint32_t* b){
    asm volatile("mma.sync.aligned.m16n8k16.row.col.f32.bf16.bf16.f32 "
        "{%0,%1,%2,%3},{%4,%5,%6,%7},{%8,%9},{%0,%1,%2,%3};"
        : "+f"(d[0]),"+f"(d[1]),"+f"(d[2]),"+f"(d[3])
        : "r"(a[0]),"r"(a[1]),"r"(a[2]),"r"(a[3]),"r"(b[0]),"r"(b[1]));
}
__device__ __forceinline__ void cpasync16(uint32_t s, const void* g){
    asm volatile("cp.async.cg.shared.global [%0],[%1],16;" :: "r"(s), "l"(g));
}
__device__ __forceinline__ void cpcommit(){ asm volatile("cp.async.commit_group;"); }
template<int N> __device__ __forceinline__ void cpwait(){
    asm volatile("cp.async.wait_group %0;" :: "n"(N));
}

// merged prep: weight signs (blocks 0..143, 4 elems/thread)
//            + pack 2px/thread float2 (blocks 144..535)
__global__ void prep(const float* __restrict__ x,
                     const float* __restrict__ w1, const float* __restrict__ w2){
    int blk = blockIdx.x;
    if (blk < 144){
        int base_i = (blk*256 + threadIdx.x)*4;
        #pragma unroll
        for (int q=0;q<4;q++){
            int i = base_i + q;
            if (i >= 9*128*128) break;
            int c = i & 127;
            int o = (i >> 7) & 127;
            int t = i >> 14;
            int s = ((o*128 + c)*3 + t/3)*3 + (t%3);
            float a = w1[s], b = w2[s];
            g_w1[i] = __float2bfloat16((a>0.f)?1.f:((a<0.f)?-1.f:0.f));
            g_w2[i] = __float2bfloat16((b>0.f)?1.f:((b<0.f)?-1.f:0.f));
        }
    } else {
        int p2 = (blk-144)*256 + threadIdx.x;        // group of 2 pixels
        if (p2 >= Bn*HWn/2) return;
        int b   = p2 / (HWn/2);
        int hw  = (p2 - b*(HWn/2)) * 2;
        const float* base = x + (size_t)b*Cn*HWn + hw;
        uint32_t w[2][4] = {};
        #pragma unroll
        for (int c=0;c<128;c++){
            float2 v = *(const float2*)(base + (size_t)c*HWn);
            uint32_t bit = 1u << (c & 31);
            int g = c >> 5;
            if (v.x < 0.f) w[0][g] |= bit;
            if (v.y < 0.f) w[1][g] |= bit;
        }
        #pragma unroll
        for (int k=0;k<2;k++)
            g_bits1[(size_t)b*HWn + hw + k] = make_uint4(w[k][0],w[k][1],w[k][2],w[k][3]);
    }
}

template<int PASS>
__global__ void __launch_bounds__(256,1)
conv_bin(const float* __restrict__ gamma, const float* __restrict__ beta,
         const float* __restrict__ mean,  const float* __restrict__ var,
         const float* __restrict__ xres,  float* __restrict__ out)
{
    extern __shared__ char smem[];
    char* act = smem;
    char* wsm = smem + ACT_BYTES;

    const int tid  = threadIdx.x;
    const int lane = tid & 31;
    const int warp = tid >> 5;
    const int wm   = warp & 3;
    const int wn   = warp >> 2;
    const int b    = blockIdx.y;
    const int y0   = blockIdx.x * ROWS;

    const uint4* bits_in = (PASS==1) ? g_bits1 : g_bits2;
    const __nv_bfloat16* wg = (PASS==1) ? g_w1 : g_w2;

    // prefetch weight taps 0,1 into stage buffers 0,1
    {
        const char* gsrc = (const char*)wg;
        uint32_t wb = smem_u32(wsm);
        #pragma unroll
        for (int i=0;i<8;i++){
            int e = i*256 + tid;
            cpasync16(wb + (e>>4)*W_STRIDE + (e&15)*16, gsrc + (size_t)e*16);
        }
        cpcommit();
        gsrc += 32768;
        #pragma unroll
        for (int i=0;i<8;i++){
            int e = i*256 + tid;
            cpasync16(wb + WBUF_BYTES + (e>>4)*W_STRIDE + (e&15)*16, gsrc + (size_t)e*16);
        }
        cpcommit();
    }

    // expand sign bits -> bf16 (+1/-1), pads=0
    for (int idx = tid; idx < ACT_PIX; idx += 256){
        int r  = idx / ACT_W;
        int xc = idx - r*ACT_W;
        int gy = y0 - 1 + r;
        int gx = xc - 1;
        uint4 bw = make_uint4(0,0,0,0);
        bool valid = ((unsigned)gy < (unsigned)Hn) && ((unsigned)gx < (unsigned)Wn);
        if (valid) bw = bits_in[(b*Hn + gy)*Wn + gx];
        uint32_t* dst = (uint32_t*)(act + (size_t)idx*ACT_STRIDE);
        uint32_t arr[4] = {bw.x, bw.y, bw.z, bw.w};
        #pragma unroll
        for (int g=0;g<4;g++){
            uint32_t bwv = arr[g];
            #pragma unroll
            for (int j=0;j<16;j++){
                uint32_t b2 = (bwv >> (2*j)) & 3u;
                uint32_t pr = valid ? (0x3F803F80u | ((b2&1u)<<15) | ((b2>>1)<<31)) : 0u;
                dst[g*16 + j] = pr;
            }
        }
    }

    const uint32_t act_base = smem_u32(act);
    const uint32_t w_base   = smem_u32(wsm);
    const uint32_t aoff = (uint32_t)(wm*32 + (lane&15))*W_STRIDE + (uint32_t)(lane>>4)*16;

    float acc[2][14][4];
    #pragma unroll
    for (int i=0;i<2;i++)
        #pragma unroll
        for (int j=0;j<14;j++)
            #pragma unroll
            for (int e=0;e<4;e++) acc[i][j][e] = 0.f;

    const int bsel = (lane >> 4) & 1;
    const int brow = lane & 7;
    const int bk16 = (lane >> 3) & 1;

    for (int t=0; t<9; ++t){
        cpwait<1>();
        __syncthreads();    // tap t visible; tap t-1 reads done

        if (t+2 < 9){
            const char* gsrc = (const char*)(wg + (size_t)(t+2)*16384);
            uint32_t sdst = w_base + (uint32_t)((t+2)%NSTAGE)*WBUF_BYTES;
            #pragma unroll
            for (int i=0;i<8;i++){
                int e = i*256 + tid;
                cpasync16(sdst + (e>>4)*W_STRIDE + (e&15)*16, gsrc + (size_t)e*16);
            }
        }
        cpcommit();

        const int dy = t/3, dx = t - dy*3;
        const uint32_t wb = w_base + (uint32_t)(t%NSTAGE)*WBUF_BYTES + aoff;

        uint32_t baddr[7];
        #pragma unroll
        for (int m=0;m<7;m++){
            int j  = 2*m + bsel;
            int ryj = wn*2 + ((j>=7)?1:0);
            int xs  = (j - ((j>=7)?7:0))*8;
            int pix0 = (ryj + dy)*ACT_W + xs + dx;
            baddr[m] = act_base + (uint32_t)(pix0 + brow)*ACT_STRIDE
                     + (uint32_t)bk16*16;
        }

        #pragma unroll
        for (int ks=0; ks<8; ks++){
            uint32_t a0[4], a1[4];
            ldsm4(a0, wb + ks*32);
            ldsm4(a1, wb + 16*W_STRIDE + ks*32);
            uint32_t bf[7][4];
            #pragma unroll
            for (int m=0;m<7;m++) ldsm4(bf[m], baddr[m] + ks*32);
            #pragma unroll
            for (int m=0;m<7;m++){
                mma16816(acc[0][2*m  ], a0, &bf[m][0]);
                mma16816(acc[0][2*m+1], a0, &bf[m][2]);
                mma16816(acc[1][2*m  ], a1, &bf[m][0]);
                mma16816(acc[1][2*m+1], a1, &bf[m][2]);
            }
        }
    }

    const int gr = lane >> 2;
    const int ct = lane & 3;
    float inv[4], bia[4];
    #pragma unroll
    for (int k=0;k<4;k++){
        int o = wm*32 + (k>>1)*16 + (k&1)*8 + gr;
        float iv = gamma[o] / sqrtf(var[o] + 1e-5f);
        inv[k] = iv;
        bia[k] = beta[o] - mean[o]*iv;
    }

    if (PASS == 2){
        #pragma unroll
        for (int mf=0; mf<2; mf++){
            #pragma unroll
            for (int j=0;j<14;j++){
                int ry = wn*2 + ((j>=7)?1:0);
                int xx = (j - ((j>=7)?7:0))*8 + ct*2;
                int y  = y0 + ry;
                #pragma unroll
                for (int h=0;h<2;h++){
                    int o = wm*32 + mf*16 + h*8 + gr;
                    int k = mf*2 + h;
                    size_t base = ((size_t)(b*Cn + o)*Hn + y)*Wn + xx;
                    float2 rv = *(const float2*)&xres[base];
                    float2 ov;
                    ov.x = fminf(fmaxf(__fadd_rn(__fmul_rn(acc[mf][j][h*2  ], inv[k]), bia[k]) + rv.x, -1.0f), 1.0f);
                    ov.y = fminf(fmaxf(__fadd_rn(__fmul_rn(acc[mf][j][h*2+1], inv[k]), bia[k]) + rv.y, -1.0f), 1.0f);
                    __stcs((float2*)&out[base], ov);   // evict-first: keep L2 for xres
                }
            }
        }
    } else {
        char* stage = wsm;   // weights no longer needed
        __syncthreads();     // all warps done reading weight buffers
        #pragma unroll
        for (int mf=0; mf<2; mf++){
            #pragma unroll
            for (int j=0;j<14;j++){
                int nb = wn*112 + j*8 + ct*2;
                #pragma unroll
                for (int h=0;h<2;h++){
                    int o = wm*32 + mf*16 + h*8 + gr;
                    int k = mf*2 + h;
                    #pragma unroll
                    for (int cc=0; cc<2; cc++){
                        float v = __fadd_rn(__fmul_rn(acc[mf][j][h*2+cc], inv[k]), bia[k]);
                        stage[(size_t)(nb+cc)*STAGE_STRIDE + o] = (v < 0.f) ? (char)1 : (char)0;
                    }
                }
            }
        }
        __syncthreads();
        if (tid < TILE_N){
            int n  = tid;
            int ry = n / 56;
            int xx = n - ry*56;
            int y  = y0 + ry;
            const uint32_t* src = (const uint32_t*)(stage + (size_t)n*STAGE_STRIDE);
            uint32_t wd[4];
            #pragma unroll
            for (int g=0; g<4; g++){
                uint32_t wv = 0;
                #pragma unroll
                for (int i=0;i<8;i++){
                    unsigned nib = __dp4a(src[g*8 + i], 0x08040201u, 0u);
                    wv |= nib << (4*i);
                }
                wd[g] = wv;
            }
            g_bits2[(b*Hn + y)*Wn + xx] = make_uint4(wd[0],wd[1],wd[2],wd[3]);
        }
    }
}

extern "C" void kernel_launch(void* const* d_in, const int* in_sizes, int n_in,
                              void* d_out, int out_size)
{
    const float* x      = (const float*)d_in[0];
    const float* w1     = (const float*)d_in[1];
    const float* w2     = (const float*)d_in[2];
    const float* gamma1 = (const float*)d_in[3];
    const float* beta1  = (const float*)d_in[4];
    const float* mean1  = (const float*)d_in[5];
    const float* var1   = (const float*)d_in[6];
    const float* gamma2 = (const float*)d_in[7];
    const float* beta2  = (const float*)d_in[8];
    const float* mean2  = (const float*)d_in[9];
    const float* var2   = (const float*)d_in[10];
    float* out = (float*)d_out;

    cudaFuncSetAttribute(conv_bin<1>, cudaFuncAttributeMaxDynamicSharedMemorySize, SMEM_BYTES);
    cudaFuncSetAttribute(conv_bin<2>, cudaFuncAttributeMaxDynamicSharedMemorySize, SMEM_BYTES);

    prep<<<536, 256>>>(x, w1, w2);

    dim3 grid(Hn/ROWS, Bn);
    conv_bin<1><<<grid, 256, SMEM_BYTES>>>(gamma1, beta1, mean1, var1, x, out);
    conv_bin<2><<<grid, 256, SMEM_BYTES>>>(gamma2, beta2, mean2, var2, x, out);
}